// round 10
// baseline (speedup 1.0000x reference)
#include <cuda_runtime.h>

// CrossAttention_47502338294587 — algebraic collapse:
// out[b,t,:] = ((vf @ Wv + bv) @ Wp + bp)[b,:]  (K/V broadcast over T ->
// uniform softmax -> y == v; independent of x, Wq, Wk).
//
// Measured invariant across R1..R9: every design converges to ~15us =
// 8MB of weights at ~550GB/s, as TWO serialized 4MB in-flight-limited read
// phases (~7us each, grid-size independent). This version OVERLAPS the two
// weight streams via grid role-split:
//   CTAs 0..255   (role A, (cg,ks)): fetch Wv tile at t=0 -> part1, flag.
//   CTAs 256..511 (role B, (cg,ks)): fetch Wp tile INTO REGS at t=0
//       (concurrent with Wv stream), spin on part1 flags, fold vv, FMA,
//       -> part2, flag.
//   All 512: phase C — fold row slice, write 32KB of output (STG.128).
// Co-residency: launch_bounds(256,4) => regs<=64 => 4 CTA/SM => 592>=512.

static constexpr int C    = 1024;
static constexpr int B    = 4;
static constexpr int T    = 1024;
static constexpr int KS   = 8;       // k-splits (128 k-rows per CTA)
static constexpr int GRID = 512;

__device__ float    g_part1[KS * B * C];   // 128 KB (L2-resident)
__device__ float    g_part2[KS * B * C];   // 128 KB
__device__ unsigned g_cnt1[32];            // part1 column-group ready counts
__device__ unsigned g_cnt2[32];            // part2 column-group ready counts
__device__ unsigned g_done = 0;

__device__ __forceinline__ void wait_count(volatile unsigned* p, unsigned target)
{
    while (*p < target) __nanosleep(64);
}

__global__ void __launch_bounds__(256, 4) fused_kernel(
    const float* __restrict__ vf,   // [B][C]
    const float* __restrict__ Wv,   // [C][C]
    const float* __restrict__ bv,   // [C]
    const float* __restrict__ Wp,   // [C][C]
    const float* __restrict__ bp,   // [C]
    float* __restrict__ out)        // [B][T][C]
{
    __shared__ float  s_in[B][128];    // 2 KB  (vf tile / vv tile)
    __shared__ float4 s_red[256][B];   // 16 KB
    __shared__ float  s_rowf[32];

    const int t  = threadIdx.x;
    const int f4 = t & 7;              // float4 column within 32-col group
    const int kr = t >> 3;             // 0..31

    const int  blk   = blockIdx.x;
    const bool roleB = blk >= 256;
    const int  r     = roleB ? blk - 256 : blk;
    const int  cg    = r & 31;         // column group
    const int  ks    = r >> 5;         // 0..7 k-split
    const int  k0    = ks * 128;

    // ---- BOTH weight streams issue at t=0 (this is the whole point) ----
    const float4* W4 = (const float4*)(roleB ? Wp : Wv);
    float4 w[4];
    #pragma unroll
    for (int i = 0; i < 4; i++)        // 4 independent full-line LDG.128
        w[i] = W4[(size_t)(k0 + kr + 32 * i) * 256 + cg * 8 + f4];

    if (!roleB) {
        // ============ Role A: partials of vf @ Wv ============
        #pragma unroll
        for (int i = 0; i < 2; i++) {  // stage vf k-tile (512 values)
            const int e = t + 256 * i;
            s_in[e >> 7][e & 127] = vf[(e >> 7) * C + k0 + (e & 127)];
        }
        __syncthreads();

        #pragma unroll
        for (int b = 0; b < B; b++) {
            float4 a = make_float4(0.f, 0.f, 0.f, 0.f);
            #pragma unroll
            for (int i = 0; i < 4; i++) {
                const float s = s_in[b][kr + 32 * i];
                a.x = fmaf(s, w[i].x, a.x);
                a.y = fmaf(s, w[i].y, a.y);
                a.z = fmaf(s, w[i].z, a.z);
                a.w = fmaf(s, w[i].w, a.w);
            }
            s_red[t][b] = a;
        }
        __syncthreads();

        #pragma unroll
        for (int off = 16; off > 0; off >>= 1) {   // reduce over kr
            if (kr < off) {
                #pragma unroll
                for (int b = 0; b < B; b++) {
                    float4 a = s_red[t][b];
                    const float4 o = s_red[t + off * 8][b];
                    a.x += o.x; a.y += o.y; a.z += o.z; a.w += o.w;
                    s_red[t][b] = a;
                }
            }
            __syncthreads();
        }

        if (t < 8) {
            #pragma unroll
            for (int b = 0; b < B; b++)
                ((float4*)g_part1)[(ks * B + b) * 256 + cg * 8 + t] = s_red[t][b];
            __threadfence();               // publish tile before flagging
        }
        __syncthreads();
        if (t == 0) atomicAdd(&g_cnt1[cg], 1u);
    } else {
        // ===== Role B: Wp already in regs; wait for vv inputs, then FMA =====
        float bvv[2];
        #pragma unroll
        for (int i = 0; i < 2; i++) {
            const int e = t + 256 * i;
            bvv[i] = bv[k0 + (e & 127)];
        }

        if (t < 4) wait_count(&g_cnt1[4 * ks + t], KS);  // our 4 producer groups
        __syncthreads();
        __threadfence();                   // acquire part1 tiles

        #pragma unroll
        for (int i = 0; i < 2; i++) {      // fold vv k-tile (16 indep __ldcg)
            const int e  = t + 256 * i;
            const int b  = e >> 7;
            const int kk = e & 127;
            float v = bvv[i];
            #pragma unroll
            for (int s = 0; s < KS; s++)
                v += __ldcg(&g_part1[(s * B + b) * C + k0 + kk]);
            s_in[b][kk] = v;
        }
        __syncthreads();

        #pragma unroll
        for (int b = 0; b < B; b++) {
            float4 a = make_float4(0.f, 0.f, 0.f, 0.f);
            #pragma unroll
            for (int i = 0; i < 4; i++) {
                const float s = s_in[b][kr + 32 * i];
                a.x = fmaf(s, w[i].x, a.x);
                a.y = fmaf(s, w[i].y, a.y);
                a.z = fmaf(s, w[i].z, a.z);
                a.w = fmaf(s, w[i].w, a.w);
            }
            s_red[t][b] = a;
        }
        __syncthreads();

        #pragma unroll
        for (int off = 16; off > 0; off >>= 1) {
            if (kr < off) {
                #pragma unroll
                for (int b = 0; b < B; b++) {
                    float4 a = s_red[t][b];
                    const float4 o = s_red[t + off * 8][b];
                    a.x += o.x; a.y += o.y; a.z += o.z; a.w += o.w;
                    s_red[t][b] = a;
                }
            }
            __syncthreads();
        }

        if (t < 8) {
            #pragma unroll
            for (int b = 0; b < B; b++)
                ((float4*)g_part2)[(ks * B + b) * 256 + cg * 8 + t] = s_red[t][b];
            __threadfence();
        }
        __syncthreads();
        if (t == 0) atomicAdd(&g_cnt2[cg], 1u);
    }

    // ===== Phase C (all 512 CTAs): fold row slice, broadcast-write =====
    {
        const int b   = blk >> 7;            // 0..3
        const int cg2 = (blk >> 2) & 31;     // 0..31
        const int tq  = blk & 3;             // t-quarter (256 rows)

        float bpv = 0.f;
        if (t < 32) bpv = bp[cg2 * 32 + t];  // prefetch before wait

        if (t == 0) wait_count(&g_cnt2[cg2], KS);
        __syncthreads();
        __threadfence();                     // acquire part2 tiles

        if (t < 32) {
            const int c = cg2 * 32 + t;
            float v = bpv;
            #pragma unroll
            for (int s = 0; s < KS; s++)
                v += __ldcg(&g_part2[(s * B + b) * C + c]);
            s_rowf[t] = v;
        }
        __syncthreads();

        const float4 rr = ((const float4*)s_rowf)[f4];
        float4* o4 = (float4*)out;
        const size_t base = ((size_t)b * T + tq * 256) * 256 + cg2 * 8 + f4;
        #pragma unroll
        for (int i = 0; i < 8; i++)          // rows kr, kr+32, ..., kr+224
            o4[base + (size_t)(kr + 32 * i) * 256] = rr;
    }

    // ===== Replay-safe flag reset by the last CTA to finish =====
    __syncthreads();
    if (t == 0) {
        const unsigned d = atomicAdd(&g_done, 1u);
        if (d == GRID - 1) {
            #pragma unroll
            for (int i = 0; i < 32; i++) { g_cnt1[i] = 0; g_cnt2[i] = 0; }
            __threadfence();
            g_done = 0;
        }
    }
}

extern "C" void kernel_launch(void* const* d_in, const int* in_sizes, int n_in,
                              void* d_out, int out_size)
{
    (void)in_sizes; (void)n_in; (void)out_size;
    const float* vf = (const float*)d_in[1];  // visual_features [B,C]
    const float* Wv = (const float*)d_in[6];
    const float* bv = (const float*)d_in[7];
    const float* Wp = (const float*)d_in[8];
    const float* bp = (const float*)d_in[9];
    float* out = (float*)d_out;

    fused_kernel<<<GRID, 256>>>(vf, Wv, bv, Wp, bp, out);
}

// round 11
// speedup vs baseline: 1.1194x; 1.1194x over previous
#include <cuda_runtime.h>

// CrossAttention_47502338294587 — algebraic collapse:
// out[b,t,:] = ((vf @ Wv + bv) @ Wp + bp)[b,:]  (K/V broadcast over T ->
// uniform softmax -> y == v; independent of x, Wq, Wk).
//
// Measured across R1-R10: persistent/fused variants (barriers, flags,
// role-split overlap) all lose to the plain 3-kernel pipeline (14.8us).
// Aggregate weight-read throughput is concurrency-insensitive (~550GB/s),
// so this round keeps the winning 3-kernel structure and fixes its two
// measured defects: 128-CTA grid (<148 SMs) and interleaved load->FMA
// (MLP_eff ~2-3). Now: grid 256 (all SMs), 4 front-batched LDG.128/thread.
//  K1 gemm_a : (cg,ks) partials of vf@Wv -> part1        (Wv read once)
//  K2 gemm_b : folds (bv+sum part1) while Wp loads fly -> part2 (Wp once)
//  K3 bcast  : folds (bp+sum part2), broadcast-writes 16MB (STG.128)
// Launch boundaries are the syncs. No atomics. Fixed summation order.

static constexpr int C  = 1024;
static constexpr int B  = 4;
static constexpr int T  = 1024;
static constexpr int KS = 8;          // k-splits: 128 k-rows per CTA

__device__ float g_part1[KS * B * C];   // 128 KB (L2-resident)
__device__ float g_part2[KS * B * C];   // 128 KB

// ---------------- K1: partials of vf @ Wv ----------------
__global__ void __launch_bounds__(256) gemm_a(
    const float* __restrict__ vf,     // [B][C]
    const float* __restrict__ W,      // [C][C]
    float* __restrict__ part)         // [KS][B][C]
{
    __shared__ float  s_in[B][128];   // 2 KB
    __shared__ float4 s_red[256][B];  // 16 KB

    const int t  = threadIdx.x;
    const int f4 = t & 7;             // float4 col within 32-col group
    const int kr = t >> 3;            // 0..31
    const int cg = blockIdx.x;        // 0..31
    const int ks = blockIdx.y;        // 0..7
    const int k0 = ks * 128;

    // 4 independent full-line LDG.128, front-batched (no FMA between)
    const float4* W4 = (const float4*)W;
    float4 w[4];
    #pragma unroll
    for (int i = 0; i < 4; i++)
        w[i] = W4[(size_t)(k0 + kr + 32 * i) * 256 + cg * 8 + f4];

    #pragma unroll
    for (int i = 0; i < 2; i++) {     // stage vf k-tile (512 values)
        const int e = t + 256 * i;
        s_in[e >> 7][e & 127] = vf[(e >> 7) * C + k0 + (e & 127)];
    }
    __syncthreads();

    #pragma unroll
    for (int b = 0; b < B; b++) {
        float4 a = make_float4(0.f, 0.f, 0.f, 0.f);
        #pragma unroll
        for (int i = 0; i < 4; i++) {
            const float s = s_in[b][kr + 32 * i];
            a.x = fmaf(s, w[i].x, a.x);
            a.y = fmaf(s, w[i].y, a.y);
            a.z = fmaf(s, w[i].z, a.z);
            a.w = fmaf(s, w[i].w, a.w);
        }
        s_red[t][b] = a;
    }
    __syncthreads();

    #pragma unroll
    for (int off = 16; off > 0; off >>= 1) {     // reduce over kr
        if (kr < off) {
            #pragma unroll
            for (int b = 0; b < B; b++) {
                float4 a = s_red[t][b];
                const float4 o = s_red[t + off * 8][b];
                a.x += o.x; a.y += o.y; a.z += o.z; a.w += o.w;
                s_red[t][b] = a;
            }
        }
        __syncthreads();
    }

    if (t < 8) {
        #pragma unroll
        for (int b = 0; b < B; b++)
            ((float4*)part)[(ks * B + b) * 256 + cg * 8 + t] = s_red[t][b];
    }
}

// ------- K2: folds vv = bv + sum(part1); partials of vv @ Wp -------
__global__ void __launch_bounds__(256) gemm_b(
    const float* __restrict__ bv,     // [C]
    const float* __restrict__ W,      // Wp [C][C]
    float* __restrict__ part)         // part2 [KS][B][C]
{
    __shared__ float  s_in[B][128];
    __shared__ float4 s_red[256][B];

    const int t  = threadIdx.x;
    const int f4 = t & 7;
    const int kr = t >> 3;
    const int cg = blockIdx.x;
    const int ks = blockIdx.y;
    const int k0 = ks * 128;

    // Wp loads first (independent of the fold below -> overlap DRAM latency)
    const float4* W4 = (const float4*)W;
    float4 w[4];
    #pragma unroll
    for (int i = 0; i < 4; i++)
        w[i] = W4[(size_t)(k0 + kr + 32 * i) * 256 + cg * 8 + f4];

    #pragma unroll
    for (int i = 0; i < 2; i++) {     // fold vv k-tile: 2 x (bias + 8 indep loads)
        const int e  = t + 256 * i;
        const int b  = e >> 7;
        const int kk = e & 127;
        float v = bv[k0 + kk];
        #pragma unroll
        for (int s = 0; s < KS; s++)
            v += g_part1[(s * B + b) * C + k0 + kk];
        s_in[b][kk] = v;
    }
    __syncthreads();

    #pragma unroll
    for (int b = 0; b < B; b++) {
        float4 a = make_float4(0.f, 0.f, 0.f, 0.f);
        #pragma unroll
        for (int i = 0; i < 4; i++) {
            const float s = s_in[b][kr + 32 * i];
            a.x = fmaf(s, w[i].x, a.x);
            a.y = fmaf(s, w[i].y, a.y);
            a.z = fmaf(s, w[i].z, a.z);
            a.w = fmaf(s, w[i].w, a.w);
        }
        s_red[t][b] = a;
    }
    __syncthreads();

    #pragma unroll
    for (int off = 16; off > 0; off >>= 1) {
        if (kr < off) {
            #pragma unroll
            for (int b = 0; b < B; b++) {
                float4 a = s_red[t][b];
                const float4 o = s_red[t + off * 8][b];
                a.x += o.x; a.y += o.y; a.z += o.z; a.w += o.w;
                s_red[t][b] = a;
            }
        }
        __syncthreads();
    }

    if (t < 8) {
        #pragma unroll
        for (int b = 0; b < B; b++)
            ((float4*)part)[(ks * B + b) * 256 + cg * 8 + t] = s_red[t][b];
    }
}

// ------- K3: fold row slice from part2 (+bp), broadcast-write -------
// grid 512 = (b 4) x (cg2 32) x (tq 4); CTA writes 256 rows x 32 cols.
__global__ void __launch_bounds__(256) bcast_kernel(
    const float* __restrict__ bp, float* __restrict__ out)
{
    __shared__ float s_rowf[32];

    const int t   = threadIdx.x;
    const int f4  = t & 7;
    const int kr  = t >> 3;
    const int b   = blockIdx.x >> 7;          // 0..3
    const int cg2 = (blockIdx.x >> 2) & 31;   // 0..31
    const int tq  = blockIdx.x & 3;           // t-quarter (256 rows)

    if (t < 32) {
        const int c = cg2 * 32 + t;
        float v = bp[c];
        #pragma unroll
        for (int s = 0; s < KS; s++)          // 8 independent loads
            v += g_part2[(s * B + b) * C + c];
        s_rowf[t] = v;
    }
    __syncthreads();

    const float4 r = ((const float4*)s_rowf)[f4];
    float4* o4 = (float4*)out;
    const size_t base = ((size_t)b * T + tq * 256) * 256 + cg2 * 8 + f4;
    #pragma unroll
    for (int i = 0; i < 8; i++)               // rows kr, kr+32, ..., kr+224
        o4[base + (size_t)(kr + 32 * i) * 256] = r;
}

extern "C" void kernel_launch(void* const* d_in, const int* in_sizes, int n_in,
                              void* d_out, int out_size)
{
    (void)in_sizes; (void)n_in; (void)out_size;
    const float* vf = (const float*)d_in[1];  // visual_features [B,C]
    const float* Wv = (const float*)d_in[6];
    const float* bv = (const float*)d_in[7];
    const float* Wp = (const float*)d_in[8];
    const float* bp = (const float*)d_in[9];
    float* out = (float*)d_out;

    float *p1, *p2;
    cudaGetSymbolAddress((void**)&p1, g_part1);
    cudaGetSymbolAddress((void**)&p2, g_part2);

    const dim3 g(32, KS);                     // 256 CTAs (>= 148 SMs)
    gemm_a<<<g, 256>>>(vf, Wv, p1);
    gemm_b<<<g, 256>>>(bv, Wp, p2);
    bcast_kernel<<<512, 256>>>(bp, out);
}